// round 1
// baseline (speedup 1.0000x reference)
#include <cuda_runtime.h>
#include <math.h>

// Problem constants (fixed shapes from reference)
#define T_TOKENS 1024      // B*S = 2*512
#define H_DIM    2048
#define I_DIM    1408
#define SI_DIM   5632
#define NE       8

#define BM 64
#define BN 64
#define BK 16

// ---------------------------------------------------------------------------
// Scratch (no cudaMalloc allowed -> __device__ globals)
// ---------------------------------------------------------------------------
__device__ int   g_cnt[NE];
__device__ int   g_tok [NE * T_TOKENS];
__device__ int   g_slot[NE * T_TOKENS];
__device__ float g_wt  [NE * T_TOKENS];
__device__ float g_sgate[T_TOKENS];
__device__ float g_act  [(size_t)NE * T_TOKENS * I_DIM];       // silu(g)*u per expert row
__device__ float g_shact[(size_t)T_TOKENS * SI_DIM];           // shared expert intermediate
__device__ float g_contrib[(size_t)T_TOKENS * 2 * H_DIM];      // per (token, k-slot) expert output * weight

// ---------------------------------------------------------------------------
__global__ void zero_cnt_kernel() {
    if (threadIdx.x < NE) g_cnt[threadIdx.x] = 0;
}

// Router: logits, softmax, top-2 selection, per-expert token lists, shared gate
__global__ __launch_bounds__(256) void router_kernel(
    const float* __restrict__ hidden,
    const float* __restrict__ gate_w,          // [H, E]
    const float* __restrict__ shared_gate_w,   // [H]
    float* __restrict__ out_logits)            // [T, E]
{
    const int t = blockIdx.x;
    __shared__ float sh[H_DIM];
    __shared__ float slog[NE];
    __shared__ float sred[256];

    const float* hrow = hidden + (size_t)t * H_DIM;
    for (int i = threadIdx.x; i < H_DIM; i += 256) sh[i] = hrow[i];
    __syncthreads();

    const int warp = threadIdx.x >> 5;
    const int lane = threadIdx.x & 31;

    // each warp computes one expert logit
    float sum = 0.f;
    for (int k = lane; k < H_DIM; k += 32) sum += sh[k] * gate_w[k * NE + warp];
    #pragma unroll
    for (int o = 16; o; o >>= 1) sum += __shfl_down_sync(0xffffffffu, sum, o);
    if (lane == 0) slog[warp] = sum;

    // shared expert gate dot product (all threads)
    float s2 = 0.f;
    for (int k = threadIdx.x; k < H_DIM; k += 256) s2 += sh[k] * shared_gate_w[k];
    sred[threadIdx.x] = s2;
    __syncthreads();
    for (int st = 128; st; st >>= 1) {
        if (threadIdx.x < st) sred[threadIdx.x] += sred[threadIdx.x + st];
        __syncthreads();
    }

    if (threadIdx.x == 0) {
        float lg[NE];
        float mx = -1e30f;
        #pragma unroll
        for (int e = 0; e < NE; ++e) { lg[e] = slog[e]; mx = fmaxf(mx, lg[e]); }
        float p[NE]; float den = 0.f;
        #pragma unroll
        for (int e = 0; e < NE; ++e) { p[e] = expf(lg[e] - mx); den += p[e]; }
        float inv = 1.f / den;
        #pragma unroll
        for (int e = 0; e < NE; ++e) {
            p[e] *= inv;
            out_logits[(size_t)t * NE + e] = lg[e];
        }
        // top-2 (strict > keeps lowest index on ties, matching jax top_k)
        int i0 = 0;
        #pragma unroll
        for (int e = 1; e < NE; ++e) if (p[e] > p[i0]) i0 = e;
        int i1 = -1;
        #pragma unroll
        for (int e = 0; e < NE; ++e) {
            if (e == i0) continue;
            if (i1 < 0 || p[e] > p[i1]) i1 = e;
        }
        int pos0 = atomicAdd(&g_cnt[i0], 1);
        g_tok [i0 * T_TOKENS + pos0] = t;
        g_slot[i0 * T_TOKENS + pos0] = 0;
        g_wt  [i0 * T_TOKENS + pos0] = p[i0];
        int pos1 = atomicAdd(&g_cnt[i1], 1);
        g_tok [i1 * T_TOKENS + pos1] = t;
        g_slot[i1 * T_TOKENS + pos1] = 1;
        g_wt  [i1 * T_TOKENS + pos1] = p[i1];

        g_sgate[t] = 1.f / (1.f + expf(-sred[0]));
    }
}

// ---------------------------------------------------------------------------
// Expert gate+up GEMM (gathered rows), fused SiLU(g)*u epilogue.
// A: hidden[tok[m], :]  (M=cnt[e], K=H)   B: w_gate/w_up [H, I]
// ---------------------------------------------------------------------------
__global__ __launch_bounds__(256) void gateup_expert_kernel(
    const float* __restrict__ hidden,
    const float* __restrict__ w_gate,
    const float* __restrict__ w_up)
{
    const int e = blockIdx.z;
    const int cnt = g_cnt[e];
    const int m0 = blockIdx.y * BM;
    if (m0 >= cnt) return;
    const int n0 = blockIdx.x * BN;

    __shared__ float As[BK][BM + 4];
    __shared__ float Bg[BK][BN];
    __shared__ float Bu[BK][BN];

    const int tid = threadIdx.x;
    const int tx = tid & 15, ty = tid >> 4;

    const int arow = tid >> 2;
    const int akk  = (tid & 3) * 4;
    const int gm = m0 + arow;
    const int tok = (gm < cnt) ? g_tok[e * T_TOKENS + gm] : 0;
    const float* arow_ptr = hidden + (size_t)tok * H_DIM;

    const int bk = tid >> 4;
    const int bn = (tid & 15) * 4;
    const float* Bg_ptr = w_gate + (size_t)e * H_DIM * I_DIM + n0 + bn;
    const float* Bu_ptr = w_up   + (size_t)e * H_DIM * I_DIM + n0 + bn;

    float accg[4][4] = {}; float accu[4][4] = {};

    for (int k0 = 0; k0 < H_DIM; k0 += BK) {
        float4 av = *(const float4*)(arow_ptr + k0 + akk);
        As[akk + 0][arow] = av.x; As[akk + 1][arow] = av.y;
        As[akk + 2][arow] = av.z; As[akk + 3][arow] = av.w;
        *(float4*)&Bg[bk][bn] = *(const float4*)(Bg_ptr + (size_t)(k0 + bk) * I_DIM);
        *(float4*)&Bu[bk][bn] = *(const float4*)(Bu_ptr + (size_t)(k0 + bk) * I_DIM);
        __syncthreads();
        #pragma unroll
        for (int k = 0; k < BK; ++k) {
            float ra[4], rg[4], ru[4];
            #pragma unroll
            for (int i = 0; i < 4; ++i) ra[i] = As[k][ty * 4 + i];
            #pragma unroll
            for (int j = 0; j < 4; ++j) { rg[j] = Bg[k][tx * 4 + j]; ru[j] = Bu[k][tx * 4 + j]; }
            #pragma unroll
            for (int i = 0; i < 4; ++i)
                #pragma unroll
                for (int j = 0; j < 4; ++j) {
                    accg[i][j] += ra[i] * rg[j];
                    accu[i][j] += ra[i] * ru[j];
                }
        }
        __syncthreads();
    }

    #pragma unroll
    for (int i = 0; i < 4; ++i) {
        const int m = m0 + ty * 4 + i;
        if (m >= cnt) continue;
        float* orow = g_act + ((size_t)e * T_TOKENS + m) * I_DIM + n0 + tx * 4;
        #pragma unroll
        for (int j = 0; j < 4; ++j) {
            float g = accg[i][j], u = accu[i][j];
            orow[j] = (g / (1.f + expf(-g))) * u;
        }
    }
}

// ---------------------------------------------------------------------------
// Expert down GEMM: contrib[(tok,slot)] = w * act @ w_down[e]
// A: g_act (M=cnt[e], K=I)   B: w_down [I, H]
// ---------------------------------------------------------------------------
__global__ __launch_bounds__(256) void down_expert_kernel(
    const float* __restrict__ w_down)
{
    const int e = blockIdx.z;
    const int cnt = g_cnt[e];
    const int m0 = blockIdx.y * BM;
    if (m0 >= cnt) return;
    const int n0 = blockIdx.x * BN;

    __shared__ float As[BK][BM + 4];
    __shared__ float Bs[BK][BN];

    const int tid = threadIdx.x;
    const int tx = tid & 15, ty = tid >> 4;

    const int arow = tid >> 2;
    const int akk  = (tid & 3) * 4;
    const float* arow_ptr = g_act + ((size_t)e * T_TOKENS + m0 + arow) * I_DIM;

    const int bk = tid >> 4;
    const int bn = (tid & 15) * 4;
    const float* B_ptr = w_down + (size_t)e * I_DIM * H_DIM + n0 + bn;

    float acc[4][4] = {};

    for (int k0 = 0; k0 < I_DIM; k0 += BK) {
        float4 av = *(const float4*)(arow_ptr + k0 + akk);
        As[akk + 0][arow] = av.x; As[akk + 1][arow] = av.y;
        As[akk + 2][arow] = av.z; As[akk + 3][arow] = av.w;
        *(float4*)&Bs[bk][bn] = *(const float4*)(B_ptr + (size_t)(k0 + bk) * H_DIM);
        __syncthreads();
        #pragma unroll
        for (int k = 0; k < BK; ++k) {
            float ra[4], rb[4];
            #pragma unroll
            for (int i = 0; i < 4; ++i) ra[i] = As[k][ty * 4 + i];
            #pragma unroll
            for (int j = 0; j < 4; ++j) rb[j] = Bs[k][tx * 4 + j];
            #pragma unroll
            for (int i = 0; i < 4; ++i)
                #pragma unroll
                for (int j = 0; j < 4; ++j) acc[i][j] += ra[i] * rb[j];
        }
        __syncthreads();
    }

    #pragma unroll
    for (int i = 0; i < 4; ++i) {
        const int m = m0 + ty * 4 + i;
        if (m >= cnt) continue;
        const float w  = g_wt [e * T_TOKENS + m];
        const int tok  = g_tok[e * T_TOKENS + m];
        const int slot = g_slot[e * T_TOKENS + m];
        float* orow = g_contrib + ((size_t)tok * 2 + slot) * H_DIM + n0 + tx * 4;
        #pragma unroll
        for (int j = 0; j < 4; ++j) orow[j] = acc[i][j] * w;
    }
}

// ---------------------------------------------------------------------------
// Shared expert gate+up: shact = silu(h@sw_gate) * (h@sw_up)   [T, SI]
// ---------------------------------------------------------------------------
__global__ __launch_bounds__(256) void gateup_shared_kernel(
    const float* __restrict__ hidden,
    const float* __restrict__ sw_gate,
    const float* __restrict__ sw_up)
{
    const int m0 = blockIdx.y * BM;
    const int n0 = blockIdx.x * BN;

    __shared__ float As[BK][BM + 4];
    __shared__ float Bg[BK][BN];
    __shared__ float Bu[BK][BN];

    const int tid = threadIdx.x;
    const int tx = tid & 15, ty = tid >> 4;

    const int arow = tid >> 2;
    const int akk  = (tid & 3) * 4;
    const float* arow_ptr = hidden + (size_t)(m0 + arow) * H_DIM;

    const int bk = tid >> 4;
    const int bn = (tid & 15) * 4;
    const float* Bg_ptr = sw_gate + n0 + bn;
    const float* Bu_ptr = sw_up   + n0 + bn;

    float accg[4][4] = {}; float accu[4][4] = {};

    for (int k0 = 0; k0 < H_DIM; k0 += BK) {
        float4 av = *(const float4*)(arow_ptr + k0 + akk);
        As[akk + 0][arow] = av.x; As[akk + 1][arow] = av.y;
        As[akk + 2][arow] = av.z; As[akk + 3][arow] = av.w;
        *(float4*)&Bg[bk][bn] = *(const float4*)(Bg_ptr + (size_t)(k0 + bk) * SI_DIM);
        *(float4*)&Bu[bk][bn] = *(const float4*)(Bu_ptr + (size_t)(k0 + bk) * SI_DIM);
        __syncthreads();
        #pragma unroll
        for (int k = 0; k < BK; ++k) {
            float ra[4], rg[4], ru[4];
            #pragma unroll
            for (int i = 0; i < 4; ++i) ra[i] = As[k][ty * 4 + i];
            #pragma unroll
            for (int j = 0; j < 4; ++j) { rg[j] = Bg[k][tx * 4 + j]; ru[j] = Bu[k][tx * 4 + j]; }
            #pragma unroll
            for (int i = 0; i < 4; ++i)
                #pragma unroll
                for (int j = 0; j < 4; ++j) {
                    accg[i][j] += ra[i] * rg[j];
                    accu[i][j] += ra[i] * ru[j];
                }
        }
        __syncthreads();
    }

    #pragma unroll
    for (int i = 0; i < 4; ++i) {
        const int m = m0 + ty * 4 + i;
        float* orow = g_shact + (size_t)m * SI_DIM + n0 + tx * 4;
        #pragma unroll
        for (int j = 0; j < 4; ++j) {
            float g = accg[i][j], u = accu[i][j];
            orow[j] = (g / (1.f + expf(-g))) * u;
        }
    }
}

// ---------------------------------------------------------------------------
// Shared down GEMM + final combine:
// out[t] = sigmoid_gate[t] * (shact @ sw_down)[t] + contrib[t,0] + contrib[t,1]
// ---------------------------------------------------------------------------
__global__ __launch_bounds__(256) void down_shared_kernel(
    const float* __restrict__ sw_down,
    float* __restrict__ out)
{
    const int m0 = blockIdx.y * BM;
    const int n0 = blockIdx.x * BN;

    __shared__ float As[BK][BM + 4];
    __shared__ float Bs[BK][BN];

    const int tid = threadIdx.x;
    const int tx = tid & 15, ty = tid >> 4;

    const int arow = tid >> 2;
    const int akk  = (tid & 3) * 4;
    const float* arow_ptr = g_shact + (size_t)(m0 + arow) * SI_DIM;

    const int bk = tid >> 4;
    const int bn = (tid & 15) * 4;
    const float* B_ptr = sw_down + n0 + bn;

    float acc[4][4] = {};

    for (int k0 = 0; k0 < SI_DIM; k0 += BK) {
        float4 av = *(const float4*)(arow_ptr + k0 + akk);
        As[akk + 0][arow] = av.x; As[akk + 1][arow] = av.y;
        As[akk + 2][arow] = av.z; As[akk + 3][arow] = av.w;
        *(float4*)&Bs[bk][bn] = *(const float4*)(B_ptr + (size_t)(k0 + bk) * H_DIM);
        __syncthreads();
        #pragma unroll
        for (int k = 0; k < BK; ++k) {
            float ra[4], rb[4];
            #pragma unroll
            for (int i = 0; i < 4; ++i) ra[i] = As[k][ty * 4 + i];
            #pragma unroll
            for (int j = 0; j < 4; ++j) rb[j] = Bs[k][tx * 4 + j];
            #pragma unroll
            for (int i = 0; i < 4; ++i)
                #pragma unroll
                for (int j = 0; j < 4; ++j) acc[i][j] += ra[i] * rb[j];
        }
        __syncthreads();
    }

    #pragma unroll
    for (int i = 0; i < 4; ++i) {
        const int m = m0 + ty * 4 + i;
        const float sg = g_sgate[m];
        float* orow = out + (size_t)m * H_DIM + n0 + tx * 4;
        const float* c0 = g_contrib + ((size_t)m * 2 + 0) * H_DIM + n0 + tx * 4;
        const float* c1 = g_contrib + ((size_t)m * 2 + 1) * H_DIM + n0 + tx * 4;
        #pragma unroll
        for (int j = 0; j < 4; ++j) orow[j] = sg * acc[i][j] + c0[j] + c1[j];
    }
}

// ---------------------------------------------------------------------------
extern "C" void kernel_launch(void* const* d_in, const int* in_sizes, int n_in,
                              void* d_out, int out_size)
{
    const float* hidden        = (const float*)d_in[0];
    const float* gate_w        = (const float*)d_in[1];
    const float* w_gate        = (const float*)d_in[2];
    const float* w_up          = (const float*)d_in[3];
    const float* w_down        = (const float*)d_in[4];
    const float* sw_gate       = (const float*)d_in[5];
    const float* sw_up         = (const float*)d_in[6];
    const float* sw_down       = (const float*)d_in[7];
    const float* shared_gate_w = (const float*)d_in[8];

    float* out        = (float*)d_out;
    float* out_logits = out + (size_t)T_TOKENS * H_DIM;

    zero_cnt_kernel<<<1, 32>>>();
    router_kernel<<<T_TOKENS, 256>>>(hidden, gate_w, shared_gate_w, out_logits);
    gateup_expert_kernel<<<dim3(I_DIM / BN, T_TOKENS / BM, NE), 256>>>(hidden, w_gate, w_up);
    down_expert_kernel  <<<dim3(H_DIM / BN, T_TOKENS / BM, NE), 256>>>(w_down);
    gateup_shared_kernel<<<dim3(SI_DIM / BN, T_TOKENS / BM), 256>>>(hidden, sw_gate, sw_up);
    down_shared_kernel  <<<dim3(H_DIM / BN, T_TOKENS / BM), 256>>>(sw_down, out);
}